// round 8
// baseline (speedup 1.0000x reference)
#include <cuda_runtime.h>
#include <stdint.h>

#define N_PTS 16384
#define GS 64
#define NCELL (GS * GS * GS)          // 262144
#define CAP 16
#define OVCAP 256
#define OX (-5.5f)
#define CELL_SZ 0.171875f              // 11/64
#define INV_CELL 5.8181818f            // 64/11
#define QTPB 128
#define QBLOCKS 256                    // 2*16384 / 128

// dir 0: db = gt (queried by pred), dir 1: db = pred (queried by gt)
__device__ int      g_cnt[2][NCELL];             // per-cell count / slot cursor (2 MB)
__device__ uint16_t g_cellidx[2][NCELL * CAP];   // per-cell point indices (16 MB, sparse-hot)
__device__ float4   g_db[2][N_PTS];              // compact db coords (512 KB)
__device__ int      g_ovcnt[2];
__device__ float4   g_ovpts[2][OVCAP];           // overflow points (scanned by every query)
__device__ float    g_bsum[QBLOCKS];

__global__ void cd_zero() {
    int i = blockIdx.x * blockDim.x + threadIdx.x;
    int stride = gridDim.x * blockDim.x;
    int* c = (int*)g_cnt;
    for (int k = i; k < 2 * NCELL; k += stride) c[k] = 0;
    if (i < 2) g_ovcnt[i] = 0;
}

__device__ __forceinline__ int cell_coord(float v) {
    int c = (int)floorf((v - OX) * INV_CELL);
    return min(max(c, 0), GS - 1);
}

__global__ void cd_build(const float* __restrict__ pred, const float* __restrict__ gt) {
    int t = blockIdx.x * blockDim.x + threadIdx.x;   // 0..32767
    int dir = t >> 14;
    int i = t & (N_PTS - 1);
    const float* P = dir ? pred : gt;                 // dir0 db=gt, dir1 db=pred
    float x = P[3 * i], y = P[3 * i + 1], z = P[3 * i + 2];
    g_db[dir][i] = make_float4(x, y, z, 0.0f);
    int cx = cell_coord(x), cy = cell_coord(y), cz = cell_coord(z);
    int cell = (cz * GS + cy) * GS + cx;
    int slot = atomicAdd(&g_cnt[dir][cell], 1);
    if (slot < CAP) {
        g_cellidx[dir][cell * CAP + slot] = (uint16_t)i;
    } else {
        int o = atomicAdd(&g_ovcnt[dir], 1);
        if (o < OVCAP) g_ovpts[dir][o] = make_float4(x, y, z, 0.0f);
    }
}

__global__ void __launch_bounds__(QTPB) cd_query(
    const float* __restrict__ pred, const float* __restrict__ gt)
{
    const int t = blockIdx.x * QTPB + threadIdx.x;    // 0..32767
    const int dir = t >> 14;
    const int i = t & (N_PTS - 1);
    const float* Q = dir ? gt : pred;
    const float qx = Q[3 * i], qy = Q[3 * i + 1], qz = Q[3 * i + 2];
    const int cx = cell_coord(qx), cy = cell_coord(qy), cz = cell_coord(qz);

    const int*      __restrict__ cnts = g_cnt[dir];
    const uint16_t* __restrict__ idx  = g_cellidx[dir];
    const float4*   __restrict__ db   = g_db[dir];

    float best = 3.402823466e+38f;   // squared distance

    for (int r = 0; r <= GS; ++r) {
        if (r > 0) {
            // Cells at Chebyshev distance >= r lie outside box B_{r-1};
            // min distance from q to outside that box = min face margin.
            float bxlo = OX + (float)(cx - (r - 1)) * CELL_SZ;
            float bxhi = OX + (float)(cx + r) * CELL_SZ;
            float bylo = OX + (float)(cy - (r - 1)) * CELL_SZ;
            float byhi = OX + (float)(cy + r) * CELL_SZ;
            float bzlo = OX + (float)(cz - (r - 1)) * CELL_SZ;
            float bzhi = OX + (float)(cz + r) * CELL_SZ;
            float m = fminf(fminf(fminf(qx - bxlo, bxhi - qx),
                                  fminf(qy - bylo, byhi - qy)),
                            fminf(qz - bzlo, bzhi - qz));
            m = fmaxf(m, 0.0f);
            if (best <= m * m) break;
        }
        int zlo = max(cz - r, 0), zhi = min(cz + r, GS - 1);
        int ylo = max(cy - r, 0), yhi = min(cy + r, GS - 1);
        int xlo = max(cx - r, 0), xhi = min(cx + r, GS - 1);
        for (int z = zlo; z <= zhi; ++z) {
            int az = abs(z - cz);
            int rowz = z * GS;
            for (int y = ylo; y <= yhi; ++y) {
                int ay = max(az, abs(y - cy));
                int rowzy = (rowz + y) * GS;
                int x0, x1;
                if (ay == r) { x0 = xlo; x1 = xhi; }        // whole x-range on shell
                else         { x0 = cx - r; x1 = cx + r; }  // only the two x-faces
                for (int x = x0; x <= x1; x += (ay == r) ? 1 : (x1 - x0 > 0 ? x1 - x0 : 1)) {
                    if (x < 0 || x >= GS) continue;
                    int cell = rowzy + x;
                    int n = min(cnts[cell], CAP);
                    const uint16_t* row = idx + cell * CAP;
#pragma unroll 4
                    for (int k = 0; k < n; ++k) {
                        float4 p = db[row[k]];
                        float dx = qx - p.x, dy = qy - p.y, dz = qz - p.z;
                        float d2 = fmaf(dx, dx, fmaf(dy, dy, dz * dz));
                        best = fminf(best, d2);
                    }
                    if (x1 == x0) break;   // single-column case guard
                }
            }
        }
    }

    // Overflow points (rarely nonempty) must always be scanned.
    int on = min(g_ovcnt[dir], OVCAP);
    for (int k = 0; k < on; ++k) {
        float4 p = g_ovpts[dir][k];
        float dx = qx - p.x, dy = qy - p.y, dz = qz - p.z;
        float d2 = fmaf(dx, dx, fmaf(dy, dy, dz * dz));
        best = fminf(best, d2);
    }

    float s = sqrtf(best);

    // block sum (deterministic tree)
    __shared__ float ssum[QTPB / 32];
    for (int o = 16; o > 0; o >>= 1) s += __shfl_xor_sync(0xFFFFFFFFu, s, o);
    if ((threadIdx.x & 31) == 0) ssum[threadIdx.x >> 5] = s;
    __syncthreads();
    if (threadIdx.x == 0) {
        float tot = 0.0f;
#pragma unroll
        for (int w = 0; w < QTPB / 32; ++w) tot += ssum[w];
        g_bsum[blockIdx.x] = tot;
    }
}

__global__ void cd_final(float* __restrict__ out) {
    float s = g_bsum[threadIdx.x];   // 256 threads, 256 partials
    for (int o = 16; o > 0; o >>= 1) s += __shfl_xor_sync(0xFFFFFFFFu, s, o);
    __shared__ float ssum[8];
    if ((threadIdx.x & 31) == 0) ssum[threadIdx.x >> 5] = s;
    __syncthreads();
    if (threadIdx.x == 0) {
        float tot = 0.0f;
#pragma unroll
        for (int w = 0; w < 8; ++w) tot += ssum[w];
        out[0] = tot / (float)N_PTS;   // (sum_pred + sum_gt)/N = mean1 + mean2
    }
}

extern "C" void kernel_launch(void* const* d_in, const int* in_sizes, int n_in,
                              void* d_out, int out_size) {
    const float* pred = (const float*)d_in[0];
    const float* gt   = (const float*)d_in[1];
    float* out = (float*)d_out;

    cd_zero<<<512, 256>>>();
    cd_build<<<(2 * N_PTS) / 256, 256>>>(pred, gt);
    cd_query<<<QBLOCKS, QTPB>>>(pred, gt);
    cd_final<<<1, QBLOCKS>>>(out);
}

// round 9
// speedup vs baseline: 4.3662x; 4.3662x over previous
#include <cuda_runtime.h>
#include <stdint.h>

#define N_PTS 16384
#define GS 64
#define NCELL (GS * GS * GS)           // 262144
#define CAP 16
#define OVCAP 1024
#define OX (-5.5f)
#define CELL_SZ 0.171875f              // 11/64
#define INV_CELL 5.8181818f            // 64/11
#define QTPB 256
#define WARPS_PB (QTPB / 32)           // 8
#define QBLOCKS (2 * N_PTS / WARPS_PB) // 4096

// dir 0: db = gt (queried by pred), dir 1: db = pred (queried by gt)
__device__ int    g_cnt[2][NCELL];              // per-cell count / slot cursor (2 MB)
__device__ float4 g_cell_pts[2][NCELL * CAP];   // direct per-cell storage (sparse-hot)
__device__ int    g_ovcnt[2];
__device__ float4 g_ovpts[2][OVCAP];            // overflow points (always scanned)
__device__ float  g_bsum[QBLOCKS];

__global__ void cd_zero() {
    int i = blockIdx.x * blockDim.x + threadIdx.x;
    int stride = gridDim.x * blockDim.x;
    int* c = (int*)g_cnt;
    for (int k = i; k < 2 * NCELL; k += stride) c[k] = 0;
    if (i < 2) g_ovcnt[i] = 0;
}

__device__ __forceinline__ int cell_coord(float v) {
    int c = (int)floorf((v - OX) * INV_CELL);
    return min(max(c, 0), GS - 1);
}

__global__ void cd_build(const float* __restrict__ pred, const float* __restrict__ gt) {
    int t = blockIdx.x * blockDim.x + threadIdx.x;   // 0..32767
    int dir = t >> 14;
    int i = t & (N_PTS - 1);
    const float* P = dir ? pred : gt;                 // dir0 db=gt, dir1 db=pred
    float x = P[3 * i], y = P[3 * i + 1], z = P[3 * i + 2];
    int cx = cell_coord(x), cy = cell_coord(y), cz = cell_coord(z);
    int cell = (cz * GS + cy) * GS + cx;
    int slot = atomicAdd(&g_cnt[dir][cell], 1);
    float4 v = make_float4(x, y, z, 0.0f);
    if (slot < CAP) {
        g_cell_pts[dir][cell * CAP + slot] = v;
    } else {
        int o = atomicAdd(&g_ovcnt[dir], 1);
        if (o < OVCAP) g_ovpts[dir][o] = v;
    }
}

// One WARP per query: lanes scan cells of the expanding Chebyshev box in parallel.
__global__ void __launch_bounds__(QTPB) cd_query(
    const float* __restrict__ pred, const float* __restrict__ gt)
{
    const int wid  = (blockIdx.x * QTPB + threadIdx.x) >> 5;   // 0..32767
    const int lane = threadIdx.x & 31;
    const int dir  = wid >> 14;
    const int i    = wid & (N_PTS - 1);

    const float* Q = dir ? gt : pred;
    const float qx = Q[3 * i], qy = Q[3 * i + 1], qz = Q[3 * i + 2];  // broadcast LDG
    const int cx = cell_coord(qx), cy = cell_coord(qy), cz = cell_coord(qz);

    const int*    __restrict__ cnts = g_cnt[dir];
    const float4* __restrict__ pts  = g_cell_pts[dir];

    float best_l = 3.402823466e+38f;   // per-lane best squared distance

    for (int r = 1; r <= GS; ++r) {
        const int u = 2 * r + 1;
        const int total = u * u * u;
        // lanes tile the (2r+1)^3 box; interior (Chebyshev < r) already scanned
        for (int base = 0; base < total; base += 32) {
            int ci = base + lane;
            if (ci < total) {
                int dz = ci / (u * u);
                int rem = ci - dz * u * u;
                int dy = rem / u;
                int dx = rem - dy * u;
                int cheb = max(max(abs(dz - r), abs(dy - r)), abs(dx - r));
                int z = cz - r + dz, y = cy - r + dy, x = cx - r + dx;
                bool ok = (r == 1 || cheb == r) &&
                          (unsigned)z < GS && (unsigned)y < GS && (unsigned)x < GS;
                if (ok) {
                    int cell = (z * GS + y) * GS + x;
                    int n = min(cnts[cell], CAP);
                    const float4* row = pts + cell * CAP;
#pragma unroll 4
                    for (int k = 0; k < n; ++k) {
                        float4 p = row[k];
                        float ddx = qx - p.x, ddy = qy - p.y, ddz = qz - p.z;
                        float d2 = fmaf(ddx, ddx, fmaf(ddy, ddy, ddz * ddz));
                        best_l = fminf(best_l, d2);
                    }
                }
            }
        }
        // warp-min of current best
        float bw = best_l;
        for (int o = 16; o > 0; o >>= 1)
            bw = fminf(bw, __shfl_xor_sync(0xFFFFFFFFu, bw, o));

        // margin: min distance from q to outside the scanned box.
        // If the box reaches a grid edge, that side's cells hold ALL clamped
        // points beyond the domain -> margin on that side is +inf.
        float mxlo = (cx - r <= 0)      ? 1e30f : qx - (OX + (float)(cx - r) * CELL_SZ);
        float mxhi = (cx + r >= GS - 1) ? 1e30f : (OX + (float)(cx + r + 1) * CELL_SZ) - qx;
        float mylo = (cy - r <= 0)      ? 1e30f : qy - (OX + (float)(cy - r) * CELL_SZ);
        float myhi = (cy + r >= GS - 1) ? 1e30f : (OX + (float)(cy + r + 1) * CELL_SZ) - qy;
        float mzlo = (cz - r <= 0)      ? 1e30f : qz - (OX + (float)(cz - r) * CELL_SZ);
        float mzhi = (cz + r >= GS - 1) ? 1e30f : (OX + (float)(cz + r + 1) * CELL_SZ) - qz;
        float m = fminf(fminf(fminf(mxlo, mxhi), fminf(mylo, myhi)), fminf(mzlo, mzhi));
        m = fmaxf(m, 0.0f);
        if (bw <= m * m) break;
    }

    // overflow points (rarely nonempty), lane-parallel
    int on = min(g_ovcnt[dir], OVCAP);
    for (int k = lane; k < on; k += 32) {
        float4 p = g_ovpts[dir][k];
        float ddx = qx - p.x, ddy = qy - p.y, ddz = qz - p.z;
        float d2 = fmaf(ddx, ddx, fmaf(ddy, ddy, ddz * ddz));
        best_l = fminf(best_l, d2);
    }
    for (int o = 16; o > 0; o >>= 1)
        best_l = fminf(best_l, __shfl_xor_sync(0xFFFFFFFFu, best_l, o));

    // per-block deterministic sum of sqrt(best) over the 8 warps
    __shared__ float swarp[WARPS_PB];
    if (lane == 0) swarp[threadIdx.x >> 5] = sqrtf(best_l);
    __syncthreads();
    if (threadIdx.x == 0) {
        float tot = 0.0f;
#pragma unroll
        for (int w = 0; w < WARPS_PB; ++w) tot += swarp[w];
        g_bsum[blockIdx.x] = tot;
    }
}

__global__ void cd_final(float* __restrict__ out) {
    const int t = threadIdx.x;            // 1024 threads, 4096 partials
    float s = 0.0f;
#pragma unroll
    for (int k = 0; k < QBLOCKS / 1024; ++k) s += g_bsum[t + k * 1024];
    for (int o = 16; o > 0; o >>= 1) s += __shfl_xor_sync(0xFFFFFFFFu, s, o);
    __shared__ float ssum[32];
    if ((t & 31) == 0) ssum[t >> 5] = s;
    __syncthreads();
    if (t == 0) {
        float tot = 0.0f;
#pragma unroll
        for (int w = 0; w < 32; ++w) tot += ssum[w];
        out[0] = tot / (float)N_PTS;   // (sum_pred + sum_gt)/N = mean1 + mean2
    }
}

extern "C" void kernel_launch(void* const* d_in, const int* in_sizes, int n_in,
                              void* d_out, int out_size) {
    const float* pred = (const float*)d_in[0];
    const float* gt   = (const float*)d_in[1];
    float* out = (float*)d_out;

    cd_zero<<<512, 256>>>();
    cd_build<<<(2 * N_PTS) / 256, 256>>>(pred, gt);
    cd_query<<<QBLOCKS, QTPB>>>(pred, gt);
    cd_final<<<1, 1024>>>(out);
}